// round 3
// baseline (speedup 1.0000x reference)
#include <cuda_runtime.h>
#include <cuda_bf16.h>

// ---------------- problem constants (fixed by the dataset) ----------------
#define N_NODES 50000
#define N_EDGES 250000
// dims: 300 -> 1024 -> 512 -> 256 -> 128 -> 2048

// ---------------- static device scratch (no allocation allowed) -----------
__device__ __align__(256) float g_h[(size_t)N_NODES * 2048];    // GEMM output, max width 2048
__device__ __align__(256) float g_act[(size_t)N_NODES * 1024];  // layer activations
__device__ __align__(256) float g_agg[(size_t)N_NODES * 1024];  // scatter accumulator (layers 1-4)
__device__ __align__(256) float g_dinv_out[N_NODES];
__device__ __align__(256) float g_dinv_in[N_NODES];

// ---------------- zero kernel (memset nodes don't work on __device__ globals)
__global__ void zero_kernel(float4* __restrict__ p, size_t n4) {
    size_t i = (size_t)blockIdx.x * blockDim.x + threadIdx.x;
    size_t stride = (size_t)gridDim.x * blockDim.x;
    float4 z = make_float4(0.f, 0.f, 0.f, 0.f);
    for (; i < n4; i += stride) p[i] = z;
}

// ---------------- degree kernels ----------------
__global__ void deg_kernel(const int* __restrict__ src,
                           const int* __restrict__ dst,
                           float* __restrict__ dout, float* __restrict__ din, int nE) {
    int e = blockIdx.x * blockDim.x + threadIdx.x;
    if (e >= nE) return;
    int s = src[e], d = dst[e];
    if (s >= 0 && s < N_NODES) atomicAdd(&dout[s], 1.0f);
    if (d >= 0 && d < N_NODES) atomicAdd(&din[d], 1.0f);
}

__global__ void dinv_kernel(float* __restrict__ a, float* __restrict__ b, int M) {
    int i = blockIdx.x * blockDim.x + threadIdx.x;
    if (i >= M) return;
    a[i] = rsqrtf(fmaxf(a[i], 1.0f));
    b[i] = rsqrtf(fmaxf(b[i], 1.0f));
}

// ---------------- row-scaled GEMM: C = diag(scale)*A @ W ----------------
// A: [M,K] row-major, W: [K,N] row-major, C: [M,N].
// BM=BN=64, BK=16, 256 threads, 4x4 accum per thread.
#define BM 64
#define BN 64
#define BK 16

__global__ __launch_bounds__(256)
void gemm_scaled_kernel(const float* __restrict__ A, const float* __restrict__ W,
                        const float* __restrict__ scale, float* __restrict__ C,
                        int M, int N, int K) {
    __shared__ float As[BK][BM];
    __shared__ float Bs[BK][BN];

    const int tid = threadIdx.x;
    const int bm = blockIdx.y * BM;
    const int bn = blockIdx.x * BN;
    const int tx = tid & 15;   // 0..15  -> 4 N-cols each
    const int ty = tid >> 4;   // 0..15  -> 4 M-rows each

    // Hoist per-row scale for the 4 A rows this thread loads each k-tile.
    float sc[4];
    #pragma unroll
    for (int p = 0; p < 4; p++) {
        int gr = bm + p * 16 + (tid >> 4);
        sc[p] = (gr < M) ? scale[gr] : 0.0f;
    }

    float acc[4][4] = {};

    for (int k0 = 0; k0 < K; k0 += BK) {
        // load A tile (64 rows x 16 k) scaled, transposed into As[k][m]
        #pragma unroll
        for (int p = 0; p < 4; p++) {
            int r = p * 16 + (tid >> 4);
            int c = tid & 15;
            int gr = bm + r, gc = k0 + c;
            float v = 0.0f;
            if (gr < M && gc < K) v = A[(size_t)gr * K + gc] * sc[p];
            As[c][r] = v;
        }
        // load B tile (16 k x 64 n)
        #pragma unroll
        for (int p = 0; p < 4; p++) {
            int kr = p * 4 + (tid >> 6);
            int c = tid & 63;
            int gk = k0 + kr;
            float v = 0.0f;
            if (gk < K) v = W[(size_t)gk * N + bn + c];
            Bs[kr][c] = v;
        }
        __syncthreads();

        #pragma unroll
        for (int kk = 0; kk < BK; kk++) {
            float a[4], b[4];
            #pragma unroll
            for (int i = 0; i < 4; i++) a[i] = As[kk][ty * 4 + i];
            #pragma unroll
            for (int j = 0; j < 4; j++) b[j] = Bs[kk][tx * 4 + j];
            #pragma unroll
            for (int i = 0; i < 4; i++)
                #pragma unroll
                for (int j = 0; j < 4; j++)
                    acc[i][j] = fmaf(a[i], b[j], acc[i][j]);
        }
        __syncthreads();
    }

    #pragma unroll
    for (int i = 0; i < 4; i++) {
        int gr = bm + ty * 4 + i;
        if (gr >= M) continue;
        float* crow = C + (size_t)gr * N + bn + tx * 4;
        #pragma unroll
        for (int j = 0; j < 4; j++) crow[j] = acc[i][j];
    }
}

// ---------------- edge scatter: agg[dst] += h[src] ----------------
__global__ void scatter_kernel(const float* __restrict__ h,
                               const int* __restrict__ src,
                               const int* __restrict__ dst,
                               float* __restrict__ agg, int N) {
    int e = blockIdx.x;
    int s = src[e];
    int d = dst[e];
    if ((unsigned)s >= N_NODES || (unsigned)d >= N_NODES) return;
    const float* hs = h + (size_t)s * N;
    float* ad = agg + (size_t)d * N;
    for (int n = threadIdx.x; n < N; n += blockDim.x)
        atomicAdd(&ad[n], hs[n]);
}

// ---------------- finalize: out = agg * dinv_in[m] + b[n], optional leaky ----
__global__ void finalize_kernel(const float* __restrict__ agg, const float* __restrict__ bias,
                                const float* __restrict__ dinv_in, float* __restrict__ out,
                                int M, int N, int leaky) {
    int idx = blockIdx.x * blockDim.x + threadIdx.x;
    if (idx >= M * N) return;  // M*N <= 102.4M < 2^31
    int m = idx / N;
    int n = idx - m * N;
    float v = agg[idx] * dinv_in[m] + bias[n];
    if (leaky) v = (v >= 0.0f) ? v : 0.01f * v;
    out[idx] = v;
}

// ---------------- launch ----------------
extern "C" void kernel_launch(void* const* d_in, const int* in_sizes, int n_in,
                              void* d_out, int out_size) {
    const float* x = (const float*)d_in[0];
    const int* ei = (const int*)d_in[1];   // int32: JAX default (x64 disabled)
    const float* W[5] = {(const float*)d_in[2], (const float*)d_in[4], (const float*)d_in[6],
                         (const float*)d_in[8], (const float*)d_in[10]};
    const float* B[5] = {(const float*)d_in[3], (const float*)d_in[5], (const float*)d_in[7],
                         (const float*)d_in[9], (const float*)d_in[11]};

    const int M = N_NODES;
    const int nE = N_EDGES;
    const int dims[6] = {300, 1024, 512, 256, 128, 2048};
    const int* src = ei;        // edge_index row 0
    const int* dstp = ei + nE;  // edge_index row 1

    float *hP, *actP, *aggP, *doutP, *dinP;
    cudaGetSymbolAddress((void**)&hP, g_h);
    cudaGetSymbolAddress((void**)&actP, g_act);
    cudaGetSymbolAddress((void**)&aggP, g_agg);
    cudaGetSymbolAddress((void**)&doutP, g_dinv_out);
    cudaGetSymbolAddress((void**)&dinP, g_dinv_in);

    // degrees -> dinv (zero via kernel: memset nodes unsupported on device globals)
    zero_kernel<<<64, 256>>>((float4*)doutP, N_NODES / 4);
    zero_kernel<<<64, 256>>>((float4*)dinP, N_NODES / 4);
    deg_kernel<<<(nE + 255) / 256, 256>>>(src, dstp, doutP, dinP, nE);
    dinv_kernel<<<(M + 255) / 256, 256>>>(doutP, dinP, M);

    const float* in = x;
    for (int l = 0; l < 5; l++) {
        int K = dims[l], N = dims[l + 1];

        dim3 grid(N / BN, (M + BM - 1) / BM);
        gemm_scaled_kernel<<<grid, 256>>>(in, W[l], doutP, hP, M, N, K);

        float* agg = (l == 4) ? (float*)d_out : aggP;
        size_t n4 = (size_t)M * N / 4;
        zero_kernel<<<1024, 256>>>((float4*)agg, n4);
        scatter_kernel<<<nE, 128>>>(hP, src, dstp, agg, N);

        float* outp = (l == 4) ? (float*)d_out : actP;
        int total = M * N;
        finalize_kernel<<<(total + 255) / 256, 256>>>(agg, B[l], dinP, outp, M, N, (l < 4) ? 1 : 0);
        in = outp;
    }
}

// round 5
// speedup vs baseline: 1.3579x; 1.3579x over previous
#include <cuda_runtime.h>
#include <cuda_bf16.h>
#include <cstdint>

// ---------------- problem constants ----------------
#define N_NODES 50000
#define N_EDGES 250000
// dims: 300 -> 1024 -> 512 -> 256 -> 128 -> 2048

// ---------------- static device scratch ----------------
__device__ __align__(256) float g_h[(size_t)N_NODES * 2048];    // GEMM output
__device__ __align__(256) float g_agg[(size_t)N_NODES * 1024];  // scatter accumulator (layers 1-4)
__device__ __align__(256) float g_dinv_out[N_NODES];
__device__ __align__(256) float g_dinv_in[N_NODES];

// ================= helpers =================
__device__ __forceinline__ uint32_t smem_u32(const void* p) {
    uint32_t a;
    asm("{ .reg .u64 t; cvta.to.shared.u64 t, %1; cvt.u32.u64 %0, t; }" : "=r"(a) : "l"(p));
    return a;
}

__device__ __forceinline__ void ldm_x4(uint32_t& r0, uint32_t& r1, uint32_t& r2, uint32_t& r3,
                                       uint32_t addr) {
    asm volatile("ldmatrix.sync.aligned.m8n8.x4.shared.b16 {%0,%1,%2,%3}, [%4];"
                 : "=r"(r0), "=r"(r1), "=r"(r2), "=r"(r3) : "r"(addr));
}

__device__ __forceinline__ void mma_bf16(float* d, const uint32_t* a, const uint32_t* b) {
    asm volatile("mma.sync.aligned.m16n8k16.row.col.f32.bf16.bf16.f32 "
                 "{%0,%1,%2,%3}, {%4,%5,%6,%7}, {%8,%9}, {%0,%1,%2,%3};"
                 : "+f"(d[0]), "+f"(d[1]), "+f"(d[2]), "+f"(d[3])
                 : "r"(a[0]), "r"(a[1]), "r"(a[2]), "r"(a[3]), "r"(b[0]), "r"(b[1]));
}

// fp32 -> bf16 hi/lo split, packed pair (low 16 bits = even-k element)
__device__ __forceinline__ void split2(float a, float b, uint32_t& hi, uint32_t& lo) {
    __nv_bfloat16 ah = __float2bfloat16(a);
    __nv_bfloat16 bh = __float2bfloat16(b);
    __nv_bfloat16 al = __float2bfloat16(a - __bfloat162float(ah));
    __nv_bfloat16 bl = __float2bfloat16(b - __bfloat162float(bh));
    hi = ((uint32_t)__bfloat16_as_ushort(bh) << 16) | (uint32_t)__bfloat16_as_ushort(ah);
    lo = ((uint32_t)__bfloat16_as_ushort(bl) << 16) | (uint32_t)__bfloat16_as_ushort(al);
}

// ================= bf16x3 mma.sync GEMM =================
// C[M,N] = transform(A) @ W.  A:[M,K], W:[K,N] row-major, C fp32.
// transform: layer1: a*dinv_out[m]; else: leaky(a*dinv_in[m]+bias[k])*dinv_out[m].
// CTA tile 128x128, BK=32. 8 warps, warp tile 32x64 via m16n8k16.
#define APAD 40  // bf16 row stride (80B): conflict-free ldmatrix, 16B aligned

__global__ __launch_bounds__(256)
void gemm_mma(const float* __restrict__ A, const float* __restrict__ W,
              const float* __restrict__ bias_prev,
              const float* __restrict__ dinv_in, const float* __restrict__ dinv_out,
              float* __restrict__ C, int M, int N, int K) {
    __shared__ __align__(16) __nv_bfloat16 sAh[128 * APAD];
    __shared__ __align__(16) __nv_bfloat16 sAl[128 * APAD];
    __shared__ __align__(16) __nv_bfloat16 sBh[128 * APAD];
    __shared__ __align__(16) __nv_bfloat16 sBl[128 * APAD];

    const int tid = threadIdx.x, lane = tid & 31, wid = tid >> 5;
    const int bm = blockIdx.y * 128, bn = blockIdx.x * 128;
    const int wm = (wid >> 1) * 32, wn = (wid & 1) * 64;

    const int g = lane >> 3, l8 = lane & 7;
    // ldmatrix per-lane element offsets (within tile)
    const uint32_t aoff = (uint32_t)(((g & 1) * 8 + l8) * APAD + (g >> 1) * 8);
    const uint32_t boff = (uint32_t)(((g >> 1) * 8 + l8) * APAD + (g & 1) * 8);

    const uint32_t sAh_u = smem_u32(sAh), sAl_u = smem_u32(sAl);
    const uint32_t sBh_u = smem_u32(sBh), sBl_u = smem_u32(sBl);

    float acc[2][8][4] = {};

    const int nkt = (K + 31) >> 5;
    for (int kt = 0; kt < nkt; kt++) {
        const int k0 = kt << 5;

        // ---- A tile: 128 rows x 16 k-pairs; fused transform + hi/lo split ----
        #pragma unroll
        for (int it = 0; it < 8; it++) {
            const int idx = it * 256 + tid;
            const int kp = idx & 15, r = idx >> 4;
            const int gr = bm + r, gk = k0 + kp * 2;
            float a0 = 0.f, a1 = 0.f;
            if (gr < M && gk < K) {
                float2 v = *reinterpret_cast<const float2*>(A + (size_t)gr * K + gk);
                const float dv = dinv_out[gr];
                if (bias_prev) {
                    const float di = dinv_in[gr];
                    a0 = fmaf(v.x, di, bias_prev[gk]);
                    a1 = fmaf(v.y, di, bias_prev[gk + 1]);
                    a0 = (a0 < 0.f) ? 0.01f * a0 : a0;
                    a1 = (a1 < 0.f) ? 0.01f * a1 : a1;
                    a0 *= dv; a1 *= dv;
                } else { a0 = v.x * dv; a1 = v.y * dv; }
            }
            uint32_t hi, lo; split2(a0, a1, hi, lo);
            ((uint32_t*)sAh)[r * (APAD / 2) + kp] = hi;
            ((uint32_t*)sAl)[r * (APAD / 2) + kp] = lo;
        }

        // ---- B tile: sB[n][k] = W[k][n], 128 n x 16 k-pairs ----
        #pragma unroll
        for (int it = 0; it < 8; it++) {
            const int idx = it * 256 + tid;
            const int n = idx & 127, kp = idx >> 7;
            const int gk = k0 + kp * 2;
            float w0 = 0.f, w1 = 0.f;
            if (gk < K) {
                const size_t go = (size_t)gk * N + bn + n;
                w0 = W[go]; w1 = W[go + N];
            }
            uint32_t hi, lo; split2(w0, w1, hi, lo);
            ((uint32_t*)sBh)[n * (APAD / 2) + kp] = hi;
            ((uint32_t*)sBl)[n * (APAD / 2) + kp] = lo;
        }
        __syncthreads();

        // ---- MMA: 2 k16 steps, hh + hl + lh ----
        #pragma unroll
        for (int ks = 0; ks < 2; ks++) {
            uint32_t ah[2][4], al[2][4];
            #pragma unroll
            for (int mb = 0; mb < 2; mb++) {
                const uint32_t off = (aoff + (uint32_t)(wm + mb * 16) * APAD + ks * 16) * 2;
                ldm_x4(ah[mb][0], ah[mb][1], ah[mb][2], ah[mb][3], sAh_u + off);
                ldm_x4(al[mb][0], al[mb][1], al[mb][2], al[mb][3], sAl_u + off);
            }
            #pragma unroll
            for (int nbp = 0; nbp < 4; nbp++) {
                const uint32_t off = (boff + (uint32_t)(wn + nbp * 16) * APAD + ks * 16) * 2;
                uint32_t bh[4], bl[4];
                ldm_x4(bh[0], bh[1], bh[2], bh[3], sBh_u + off);
                ldm_x4(bl[0], bl[1], bl[2], bl[3], sBl_u + off);
                #pragma unroll
                for (int h = 0; h < 2; h++) {
                    #pragma unroll
                    for (int mb = 0; mb < 2; mb++) {
                        float* d = acc[mb][nbp * 2 + h];
                        mma_bf16(d, ah[mb], bh + h * 2);
                        mma_bf16(d, ah[mb], bl + h * 2);
                        mma_bf16(d, al[mb], bh + h * 2);
                    }
                }
            }
        }
        __syncthreads();
    }

    // ---- epilogue: direct register stores ----
    const int mrow = lane >> 2, ncol = (lane & 3) * 2;
    #pragma unroll
    for (int mb = 0; mb < 2; mb++) {
        #pragma unroll
        for (int nb = 0; nb < 8; nb++) {
            const float* d = acc[mb][nb];
            const int m0 = bm + wm + mb * 16 + mrow;
            const int n = bn + wn + nb * 8 + ncol;
            if (m0 < M)
                *reinterpret_cast<float2*>(C + (size_t)m0 * N + n) = make_float2(d[0], d[1]);
            if (m0 + 8 < M)
                *reinterpret_cast<float2*>(C + (size_t)(m0 + 8) * N + n) = make_float2(d[2], d[3]);
        }
    }
}

// ================= auxiliary kernels =================
__global__ void zero_kernel(float4* __restrict__ p, size_t n4) {
    size_t i = (size_t)blockIdx.x * blockDim.x + threadIdx.x;
    size_t stride = (size_t)gridDim.x * blockDim.x;
    float4 z = make_float4(0.f, 0.f, 0.f, 0.f);
    for (; i < n4; i += stride) p[i] = z;
}

__global__ void deg_kernel(const int* __restrict__ src, const int* __restrict__ dst,
                           float* __restrict__ dout, float* __restrict__ din, int nE) {
    int e = blockIdx.x * blockDim.x + threadIdx.x;
    if (e >= nE) return;
    int s = src[e], d = dst[e];
    if ((unsigned)s < N_NODES) atomicAdd(&dout[s], 1.0f);
    if ((unsigned)d < N_NODES) atomicAdd(&din[d], 1.0f);
}

__global__ void dinv_kernel(float* __restrict__ a, float* __restrict__ b, int M) {
    int i = blockIdx.x * blockDim.x + threadIdx.x;
    if (i >= M) return;
    a[i] = rsqrtf(fmaxf(a[i], 1.0f));
    b[i] = rsqrtf(fmaxf(b[i], 1.0f));
}

// warp-per-edge scatter: agg[dst] += h[src], float4 gather + scalar RED
__global__ __launch_bounds__(256)
void scatter_kernel(const float* __restrict__ h, const int* __restrict__ src,
                    const int* __restrict__ dst, float* __restrict__ agg, int N) {
    int e = blockIdx.x * 8 + (threadIdx.x >> 5);
    if (e >= N_EDGES) return;
    int lane = threadIdx.x & 31;
    int s = src[e], d = dst[e];
    if ((unsigned)s >= N_NODES || (unsigned)d >= N_NODES) return;
    const float4* hs = (const float4*)(h + (size_t)s * N);
    float* ad = agg + (size_t)d * N;
    int n4 = N >> 2;
    for (int i = lane; i < n4; i += 32) {
        float4 v = hs[i];
        atomicAdd(ad + i * 4 + 0, v.x);
        atomicAdd(ad + i * 4 + 1, v.y);
        atomicAdd(ad + i * 4 + 2, v.z);
        atomicAdd(ad + i * 4 + 3, v.w);
    }
}

__global__ void finalize_kernel(const float* __restrict__ agg, const float* __restrict__ bias,
                                const float* __restrict__ dinv_in, float* __restrict__ out,
                                int M, int N) {
    int idx = blockIdx.x * blockDim.x + threadIdx.x;
    if (idx >= M * N) return;
    int m = idx / N;
    int n = idx - m * N;
    out[idx] = agg[idx] * dinv_in[m] + bias[n];
}

// ================= launch =================
extern "C" void kernel_launch(void* const* d_in, const int* in_sizes, int n_in,
                              void* d_out, int out_size) {
    const float* x = (const float*)d_in[0];
    const int* ei = (const int*)d_in[1];   // int32 (JAX x64 disabled)
    const float* W[5] = {(const float*)d_in[2], (const float*)d_in[4], (const float*)d_in[6],
                         (const float*)d_in[8], (const float*)d_in[10]};
    const float* B[5] = {(const float*)d_in[3], (const float*)d_in[5], (const float*)d_in[7],
                         (const float*)d_in[9], (const float*)d_in[11]};

    const int M = N_NODES;
    const int nE = N_EDGES;
    const int dims[6] = {300, 1024, 512, 256, 128, 2048};
    const int* src = ei;
    const int* dstp = ei + nE;

    float *hP, *aggP, *doutP, *dinP;
    cudaGetSymbolAddress((void**)&hP, g_h);
    cudaGetSymbolAddress((void**)&aggP, g_agg);
    cudaGetSymbolAddress((void**)&doutP, g_dinv_out);
    cudaGetSymbolAddress((void**)&dinP, g_dinv_in);

    zero_kernel<<<64, 256>>>((float4*)doutP, N_NODES / 4);
    zero_kernel<<<64, 256>>>((float4*)dinP, N_NODES / 4);
    deg_kernel<<<(nE + 255) / 256, 256>>>(src, dstp, doutP, dinP, nE);
    dinv_kernel<<<(M + 255) / 256, 256>>>(doutP, dinP, M);

    const float* in = x;
    const float* bp = nullptr;   // fused prev-layer finalize (null for layer 1)
    for (int l = 0; l < 5; l++) {
        int K = dims[l], N = dims[l + 1];

        dim3 grid(N / 128, (M + 127) / 128);
        gemm_mma<<<grid, 256>>>(in, W[l], bp, dinP, doutP, hP, M, N, K);

        float* agg = (l == 4) ? (float*)d_out : aggP;
        zero_kernel<<<1024, 256>>>((float4*)agg, (size_t)M * N / 4);
        scatter_kernel<<<(nE + 7) / 8, 256>>>(hP, src, dstp, agg, N);

        if (l == 4) {
            int total = M * N;
            finalize_kernel<<<(total + 255) / 256, 256>>>((float*)d_out, B[4], dinP, (float*)d_out, M, N);
        }
        in = aggP;
        bp = B[l];
    }
}

// round 6
// speedup vs baseline: 2.3399x; 1.7232x over previous
#include <cuda_runtime.h>
#include <cuda_bf16.h>
#include <cstdint>

// ---------------- problem constants ----------------
#define N_NODES 50000
#define N_EDGES 250000
// dims: 300 -> 1024 -> 512 -> 256 -> 128 -> 2048

// ---------------- static device scratch ----------------
__device__ __align__(256) float g_h[(size_t)N_NODES * 2048];    // GEMM output
__device__ __align__(256) float g_agg[(size_t)N_NODES * 1024];  // gather output (layers 1-4)
__device__ __align__(256) float g_dinv_out[N_NODES];
__device__ __align__(256) float g_dinv_in[N_NODES];
// CSC structures
__device__ __align__(256) int g_ideg[N_NODES];
__device__ __align__(256) int g_odeg[N_NODES];
__device__ __align__(256) int g_off[N_NODES + 4];
__device__ __align__(256) int g_cur[N_NODES];
__device__ __align__(256) int g_csc[N_EDGES];
__device__ __align__(256) int g_bsum[128];

// ================= helpers =================
__device__ __forceinline__ uint32_t smem_u32(const void* p) {
    uint32_t a;
    asm("{ .reg .u64 t; cvta.to.shared.u64 t, %1; cvt.u32.u64 %0, t; }" : "=r"(a) : "l"(p));
    return a;
}

__device__ __forceinline__ void ldm_x4(uint32_t& r0, uint32_t& r1, uint32_t& r2, uint32_t& r3,
                                       uint32_t addr) {
    asm volatile("ldmatrix.sync.aligned.m8n8.x4.shared.b16 {%0,%1,%2,%3}, [%4];"
                 : "=r"(r0), "=r"(r1), "=r"(r2), "=r"(r3) : "r"(addr));
}

__device__ __forceinline__ void mma_bf16(float* d, const uint32_t* a, const uint32_t* b) {
    asm volatile("mma.sync.aligned.m16n8k16.row.col.f32.bf16.bf16.f32 "
                 "{%0,%1,%2,%3}, {%4,%5,%6,%7}, {%8,%9}, {%0,%1,%2,%3};"
                 : "+f"(d[0]), "+f"(d[1]), "+f"(d[2]), "+f"(d[3])
                 : "r"(a[0]), "r"(a[1]), "r"(a[2]), "r"(a[3]), "r"(b[0]), "r"(b[1]));
}

// fp32 -> bf16 hi/lo split, packed pair (low 16 bits = even-k element)
__device__ __forceinline__ void split2(float a, float b, uint32_t& hi, uint32_t& lo) {
    __nv_bfloat16 ah = __float2bfloat16(a);
    __nv_bfloat16 bh = __float2bfloat16(b);
    __nv_bfloat16 al = __float2bfloat16(a - __bfloat162float(ah));
    __nv_bfloat16 bl = __float2bfloat16(b - __bfloat162float(bh));
    hi = ((uint32_t)__bfloat16_as_ushort(bh) << 16) | (uint32_t)__bfloat16_as_ushort(ah);
    lo = ((uint32_t)__bfloat16_as_ushort(bl) << 16) | (uint32_t)__bfloat16_as_ushort(al);
}

// ================= bf16x3 mma.sync GEMM (unchanged from R5) =================
#define APAD 40  // bf16 row stride (80B): conflict-free ldmatrix, 16B aligned

__global__ __launch_bounds__(256)
void gemm_mma(const float* __restrict__ A, const float* __restrict__ W,
              const float* __restrict__ bias_prev,
              const float* __restrict__ dinv_in, const float* __restrict__ dinv_out,
              float* __restrict__ C, int M, int N, int K) {
    __shared__ __align__(16) __nv_bfloat16 sAh[128 * APAD];
    __shared__ __align__(16) __nv_bfloat16 sAl[128 * APAD];
    __shared__ __align__(16) __nv_bfloat16 sBh[128 * APAD];
    __shared__ __align__(16) __nv_bfloat16 sBl[128 * APAD];

    const int tid = threadIdx.x, lane = tid & 31, wid = tid >> 5;
    const int bm = blockIdx.y * 128, bn = blockIdx.x * 128;
    const int wm = (wid >> 1) * 32, wn = (wid & 1) * 64;

    const int g = lane >> 3, l8 = lane & 7;
    const uint32_t aoff = (uint32_t)(((g & 1) * 8 + l8) * APAD + (g >> 1) * 8);
    const uint32_t boff = (uint32_t)(((g >> 1) * 8 + l8) * APAD + (g & 1) * 8);

    const uint32_t sAh_u = smem_u32(sAh), sAl_u = smem_u32(sAl);
    const uint32_t sBh_u = smem_u32(sBh), sBl_u = smem_u32(sBl);

    float acc[2][8][4] = {};

    const int nkt = (K + 31) >> 5;
    for (int kt = 0; kt < nkt; kt++) {
        const int k0 = kt << 5;

        #pragma unroll
        for (int it = 0; it < 8; it++) {
            const int idx = it * 256 + tid;
            const int kp = idx & 15, r = idx >> 4;
            const int gr = bm + r, gk = k0 + kp * 2;
            float a0 = 0.f, a1 = 0.f;
            if (gr < M && gk < K) {
                float2 v = *reinterpret_cast<const float2*>(A + (size_t)gr * K + gk);
                const float dv = dinv_out[gr];
                if (bias_prev) {
                    const float di = dinv_in[gr];
                    a0 = fmaf(v.x, di, bias_prev[gk]);
                    a1 = fmaf(v.y, di, bias_prev[gk + 1]);
                    a0 = (a0 < 0.f) ? 0.01f * a0 : a0;
                    a1 = (a1 < 0.f) ? 0.01f * a1 : a1;
                    a0 *= dv; a1 *= dv;
                } else { a0 = v.x * dv; a1 = v.y * dv; }
            }
            uint32_t hi, lo; split2(a0, a1, hi, lo);
            ((uint32_t*)sAh)[r * (APAD / 2) + kp] = hi;
            ((uint32_t*)sAl)[r * (APAD / 2) + kp] = lo;
        }

        #pragma unroll
        for (int it = 0; it < 8; it++) {
            const int idx = it * 256 + tid;
            const int n = idx & 127, kp = idx >> 7;
            const int gk = k0 + kp * 2;
            float w0 = 0.f, w1 = 0.f;
            if (gk < K) {
                const size_t go = (size_t)gk * N + bn + n;
                w0 = W[go]; w1 = W[go + N];
            }
            uint32_t hi, lo; split2(w0, w1, hi, lo);
            ((uint32_t*)sBh)[n * (APAD / 2) + kp] = hi;
            ((uint32_t*)sBl)[n * (APAD / 2) + kp] = lo;
        }
        __syncthreads();

        #pragma unroll
        for (int ks = 0; ks < 2; ks++) {
            uint32_t ah[2][4], al[2][4];
            #pragma unroll
            for (int mb = 0; mb < 2; mb++) {
                const uint32_t off = (aoff + (uint32_t)(wm + mb * 16) * APAD + ks * 16) * 2;
                ldm_x4(ah[mb][0], ah[mb][1], ah[mb][2], ah[mb][3], sAh_u + off);
                ldm_x4(al[mb][0], al[mb][1], al[mb][2], al[mb][3], sAl_u + off);
            }
            #pragma unroll
            for (int nbp = 0; nbp < 4; nbp++) {
                const uint32_t off = (boff + (uint32_t)(wn + nbp * 16) * APAD + ks * 16) * 2;
                uint32_t bh[4], bl[4];
                ldm_x4(bh[0], bh[1], bh[2], bh[3], sBh_u + off);
                ldm_x4(bl[0], bl[1], bl[2], bl[3], sBl_u + off);
                #pragma unroll
                for (int h = 0; h < 2; h++) {
                    #pragma unroll
                    for (int mb = 0; mb < 2; mb++) {
                        float* d = acc[mb][nbp * 2 + h];
                        mma_bf16(d, ah[mb], bh + h * 2);
                        mma_bf16(d, ah[mb], bl + h * 2);
                        mma_bf16(d, al[mb], bh + h * 2);
                    }
                }
            }
        }
        __syncthreads();
    }

    const int mrow = lane >> 2, ncol = (lane & 3) * 2;
    #pragma unroll
    for (int mb = 0; mb < 2; mb++) {
        #pragma unroll
        for (int nb = 0; nb < 8; nb++) {
            const float* d = acc[mb][nb];
            const int m0 = bm + wm + mb * 16 + mrow;
            const int n = bn + wn + nb * 8 + ncol;
            if (m0 < M)
                *reinterpret_cast<float2*>(C + (size_t)m0 * N + n) = make_float2(d[0], d[1]);
            if (m0 + 8 < M)
                *reinterpret_cast<float2*>(C + (size_t)(m0 + 8) * N + n) = make_float2(d[2], d[3]);
        }
    }
}

// ================= CSC build =================
__global__ void zero_int_kernel(int4* __restrict__ p, int n4) {
    int i = blockIdx.x * blockDim.x + threadIdx.x;
    int stride = gridDim.x * blockDim.x;
    int4 z = make_int4(0, 0, 0, 0);
    for (; i < n4; i += stride) p[i] = z;
}

__global__ void hist_kernel(const int* __restrict__ src, const int* __restrict__ dst,
                            int* __restrict__ odeg, int* __restrict__ ideg, int nE) {
    int e = blockIdx.x * blockDim.x + threadIdx.x;
    if (e >= nE) return;
    int s = src[e], d = dst[e];
    if ((unsigned)s < N_NODES) atomicAdd(&odeg[s], 1);
    if ((unsigned)d < N_NODES) atomicAdd(&ideg[d], 1);
}

__global__ void dinv_kernel(const int* __restrict__ odeg, const int* __restrict__ ideg,
                            float* __restrict__ dout, float* __restrict__ din, int M) {
    int i = blockIdx.x * blockDim.x + threadIdx.x;
    if (i >= M) return;
    dout[i] = rsqrtf(fmaxf((float)odeg[i], 1.0f));
    din[i] = rsqrtf(fmaxf((float)ideg[i], 1.0f));
}

#define SCAN_BS 512
#define SCAN_NB ((N_NODES + SCAN_BS - 1) / SCAN_BS)  // 98

__global__ void blocksum_kernel(const int* __restrict__ deg, int* __restrict__ bsum) {
    __shared__ int sh[SCAN_BS];
    int i = blockIdx.x * SCAN_BS + threadIdx.x;
    sh[threadIdx.x] = (i < N_NODES) ? deg[i] : 0;
    __syncthreads();
    for (int s = SCAN_BS / 2; s > 0; s >>= 1) {
        if (threadIdx.x < s) sh[threadIdx.x] += sh[threadIdx.x + s];
        __syncthreads();
    }
    if (threadIdx.x == 0) bsum[blockIdx.x] = sh[0];
}

__global__ void scanpart_kernel(int* __restrict__ bsum, int nb) {
    __shared__ int sh[256];
    int t = threadIdx.x;
    int v = (t < nb) ? bsum[t] : 0;
    sh[t] = v;
    __syncthreads();
    for (int s = 1; s < 256; s <<= 1) {
        int add = (t >= s) ? sh[t - s] : 0;
        __syncthreads();
        sh[t] += add;
        __syncthreads();
    }
    if (t < nb) bsum[t] = sh[t] - v;  // exclusive
}

__global__ void offsets_kernel(const int* __restrict__ deg, const int* __restrict__ bsum,
                               int* __restrict__ off, int* __restrict__ cur) {
    __shared__ int sh[SCAN_BS];
    int t = threadIdx.x;
    int i = blockIdx.x * SCAN_BS + t;
    int v = (i < N_NODES) ? deg[i] : 0;
    sh[t] = v;
    __syncthreads();
    for (int s = 1; s < SCAN_BS; s <<= 1) {
        int add = (t >= s) ? sh[t - s] : 0;
        __syncthreads();
        sh[t] += add;
        __syncthreads();
    }
    if (i < N_NODES) {
        int excl = sh[t] - v + bsum[blockIdx.x];
        off[i] = excl;
        cur[i] = excl;
        if (i == N_NODES - 1) off[N_NODES] = excl + v;
    }
}

__global__ void fill_kernel(const int* __restrict__ src, const int* __restrict__ dst,
                            int* __restrict__ cur, int* __restrict__ csc, int nE) {
    int e = blockIdx.x * blockDim.x + threadIdx.x;
    if (e >= nE) return;
    int s = src[e], d = dst[e];
    if ((unsigned)s >= N_NODES || (unsigned)d >= N_NODES) return;
    int pos = atomicAdd(&cur[d], 1);
    csc[pos] = s;
}

// ================= pull aggregation (no atomics) =================
// out[node] = sum_{e: dst==node} h[src_e]   (+ optional dinv_in*(.)+bias for last layer)
__global__ __launch_bounds__(256)
void gather_kernel(const float* __restrict__ h, const int* __restrict__ off,
                   const int* __restrict__ csc, float* __restrict__ out, int N4,
                   const float* __restrict__ bias, const float* __restrict__ dinv_in) {
    const int node = blockIdx.x;
    const int beg = off[node], end = off[node + 1];
    const float4* h4 = (const float4*)h;
    float4* out4 = (float4*)out + (size_t)node * N4;

    for (int c = threadIdx.x; c < N4; c += 256) {
        float4 acc = make_float4(0.f, 0.f, 0.f, 0.f);
        for (int j = beg; j < end; j++) {
            const int s = csc[j];  // warp-uniform -> broadcast load
            float4 v = h4[(size_t)s * N4 + c];
            acc.x += v.x; acc.y += v.y; acc.z += v.z; acc.w += v.w;
        }
        if (bias) {
            const float di = dinv_in[node];
            const float4 b = ((const float4*)bias)[c];
            acc.x = fmaf(acc.x, di, b.x);
            acc.y = fmaf(acc.y, di, b.y);
            acc.z = fmaf(acc.z, di, b.z);
            acc.w = fmaf(acc.w, di, b.w);
        }
        out4[c] = acc;
    }
}

// ================= launch =================
extern "C" void kernel_launch(void* const* d_in, const int* in_sizes, int n_in,
                              void* d_out, int out_size) {
    const float* x = (const float*)d_in[0];
    const int* ei = (const int*)d_in[1];   // int32 (JAX x64 disabled)
    const float* W[5] = {(const float*)d_in[2], (const float*)d_in[4], (const float*)d_in[6],
                         (const float*)d_in[8], (const float*)d_in[10]};
    const float* B[5] = {(const float*)d_in[3], (const float*)d_in[5], (const float*)d_in[7],
                         (const float*)d_in[9], (const float*)d_in[11]};

    const int M = N_NODES;
    const int nE = N_EDGES;
    const int dims[6] = {300, 1024, 512, 256, 128, 2048};
    const int* src = ei;
    const int* dstp = ei + nE;

    float *hP, *aggP, *doutP, *dinP;
    int *idegP, *odegP, *offP, *curP, *cscP, *bsumP;
    cudaGetSymbolAddress((void**)&hP, g_h);
    cudaGetSymbolAddress((void**)&aggP, g_agg);
    cudaGetSymbolAddress((void**)&doutP, g_dinv_out);
    cudaGetSymbolAddress((void**)&dinP, g_dinv_in);
    cudaGetSymbolAddress((void**)&idegP, g_ideg);
    cudaGetSymbolAddress((void**)&odegP, g_odeg);
    cudaGetSymbolAddress((void**)&offP, g_off);
    cudaGetSymbolAddress((void**)&curP, g_cur);
    cudaGetSymbolAddress((void**)&cscP, g_csc);
    cudaGetSymbolAddress((void**)&bsumP, g_bsum);

    // ---- degrees + dinv + CSC build ----
    zero_int_kernel<<<32, 256>>>((int4*)idegP, N_NODES / 4);
    zero_int_kernel<<<32, 256>>>((int4*)odegP, N_NODES / 4);
    hist_kernel<<<(nE + 255) / 256, 256>>>(src, dstp, odegP, idegP, nE);
    dinv_kernel<<<(M + 255) / 256, 256>>>(odegP, idegP, doutP, dinP, M);
    blocksum_kernel<<<SCAN_NB, SCAN_BS>>>(idegP, bsumP);
    scanpart_kernel<<<1, 256>>>(bsumP, SCAN_NB);
    offsets_kernel<<<SCAN_NB, SCAN_BS>>>(idegP, bsumP, offP, curP);
    fill_kernel<<<(nE + 255) / 256, 256>>>(src, dstp, curP, cscP, nE);

    // ---- 5 layers: GEMM (fused prev finalize) -> pull gather ----
    const float* in = x;
    const float* bp = nullptr;
    for (int l = 0; l < 5; l++) {
        int K = dims[l], N = dims[l + 1];

        dim3 grid(N / 128, (M + 127) / 128);
        gemm_mma<<<grid, 256>>>(in, W[l], bp, dinP, doutP, hP, M, N, K);

        float* agg = (l == 4) ? (float*)d_out : aggP;
        const float* fb = (l == 4) ? B[4] : nullptr;   // fuse finalize on last layer
        gather_kernel<<<M, 256>>>(hP, offP, cscP, agg, N / 4, fb, dinP);

        in = aggP;
        bp = B[l];
    }
}

// round 7
// speedup vs baseline: 3.9532x; 1.6894x over previous
#include <cuda_runtime.h>
#include <cuda_bf16.h>
#include <cstdint>

// ---------------- problem constants ----------------
#define N_NODES 50000
#define N_EDGES 250000
#define M_PAD 50048           // 391 * 128
// dims: 300 -> 1024 -> 512 -> 256 -> 128 -> 2048

// ---------------- static device scratch ----------------
__device__ __align__(256) float g_h[(size_t)N_NODES * 2048];            // GEMM output
__device__ __align__(256) __nv_bfloat16 g_Ah[(size_t)M_PAD * 1024];     // pre-split A (hi)
__device__ __align__(256) __nv_bfloat16 g_Al[(size_t)M_PAD * 1024];     // pre-split A (lo)
__device__ __align__(256) __nv_bfloat16 g_Wh[600000];                   // transposed split W (hi)
__device__ __align__(256) __nv_bfloat16 g_Wl[600000];                   // transposed split W (lo)
__device__ __align__(256) float g_dinv_out[N_NODES];
__device__ __align__(256) float g_dinv_in[N_NODES];
// CSC structures
__device__ __align__(256) int g_ideg[N_NODES];
__device__ __align__(256) int g_odeg[N_NODES];
__device__ __align__(256) int g_off[N_NODES + 4];
__device__ __align__(256) int g_cur[N_NODES];
__device__ __align__(256) int g_csc[N_EDGES];
__device__ __align__(256) int g_bsum[128];

// ================= helpers =================
__device__ __forceinline__ uint32_t smem_u32(const void* p) {
    uint32_t a;
    asm("{ .reg .u64 t; cvta.to.shared.u64 t, %1; cvt.u32.u64 %0, t; }" : "=r"(a) : "l"(p));
    return a;
}

__device__ __forceinline__ void ldm_x4(uint32_t& r0, uint32_t& r1, uint32_t& r2, uint32_t& r3,
                                       uint32_t addr) {
    asm volatile("ldmatrix.sync.aligned.m8n8.x4.shared.b16 {%0,%1,%2,%3}, [%4];"
                 : "=r"(r0), "=r"(r1), "=r"(r2), "=r"(r3) : "r"(addr));
}

__device__ __forceinline__ void mma_bf16(float* d, const uint32_t* a, const uint32_t* b) {
    asm volatile("mma.sync.aligned.m16n8k16.row.col.f32.bf16.bf16.f32 "
                 "{%0,%1,%2,%3}, {%4,%5,%6,%7}, {%8,%9}, {%0,%1,%2,%3};"
                 : "+f"(d[0]), "+f"(d[1]), "+f"(d[2]), "+f"(d[3])
                 : "r"(a[0]), "r"(a[1]), "r"(a[2]), "r"(a[3]), "r"(b[0]), "r"(b[1]));
}

// fp32 -> bf16 hi/lo split, packed pair (low 16 bits = even-k element)
__device__ __forceinline__ void split2(float a, float b, uint32_t& hi, uint32_t& lo) {
    __nv_bfloat16 ah = __float2bfloat16(a);
    __nv_bfloat16 bh = __float2bfloat16(b);
    __nv_bfloat16 al = __float2bfloat16(a - __bfloat162float(ah));
    __nv_bfloat16 bl = __float2bfloat16(b - __bfloat162float(bh));
    hi = ((uint32_t)__bfloat16_as_ushort(bh) << 16) | (uint32_t)__bfloat16_as_ushort(ah);
    lo = ((uint32_t)__bfloat16_as_ushort(bl) << 16) | (uint32_t)__bfloat16_as_ushort(al);
}

// ================= pipelined bf16x3 mma.sync GEMM =================
// C[M,N] = A @ Wt^T with A = Ah+Al [M,sA] bf16, Wt = Wh+Wl [N,sW] bf16 (k-major rows).
// CTA 128x128, BK=32, 8 warps, 2-stage cp.async double buffer.
#define APAD 40                 // bf16 row stride in smem (80B)
#define TILE_B 10240            // 128*40*2 bytes per tile
#define STAGE_B 40960           // 4 tiles
#define SMEM_TOTAL_B 81920      // 2 stages

__global__ __launch_bounds__(256)
void gemm_mma(const __nv_bfloat16* __restrict__ Ah, const __nv_bfloat16* __restrict__ Al,
              const __nv_bfloat16* __restrict__ Wh, const __nv_bfloat16* __restrict__ Wl,
              float* __restrict__ C, int M, int N, int sA, int sW) {
    extern __shared__ __nv_bfloat16 dsm[];
    const uint32_t sbase = smem_u32(dsm);

    const int tid = threadIdx.x, lane = tid & 31, wid = tid >> 5;
    const int bm = blockIdx.y * 128, bn = blockIdx.x * 128;
    const int wm = (wid >> 1) * 32, wn = (wid & 1) * 64;
    const int nkt = sA >> 5;    // sA == K_pad (multiple of 32)

    const int g = lane >> 3, l8 = lane & 7;
    const uint32_t aoff = (uint32_t)(((g & 1) * 8 + l8) * APAD + (g >> 1) * 8);
    const uint32_t boff = (uint32_t)(((g >> 1) * 8 + l8) * APAD + (g & 1) * 8);

    // per-thread loader coords: 2048 16B-chunks/stage, 8 per thread
    // idx = it*256+tid: tile=idx>>9, r=(idx&511)>>2, c=idx&3
    auto load_stage = [&](int kt, int st) {
        const int k0 = kt << 5;
        #pragma unroll
        for (int it = 0; it < 8; it++) {
            const int idx = it * 256 + tid;
            const int t = idx >> 9, rc = idx & 511;
            const int r = rc >> 2, c = rc & 3;
            const __nv_bfloat16* gsrc;
            if (t == 0)      gsrc = Ah + (size_t)(bm + r) * sA + k0 + c * 8;
            else if (t == 1) gsrc = Al + (size_t)(bm + r) * sA + k0 + c * 8;
            else if (t == 2) gsrc = Wh + (size_t)(bn + r) * sW + k0 + c * 8;
            else             gsrc = Wl + (size_t)(bn + r) * sW + k0 + c * 8;
            const uint32_t d = sbase + st * STAGE_B + t * TILE_B + r * 80 + c * 16;
            asm volatile("cp.async.ca.shared.global [%0], [%1], 16;" :: "r"(d), "l"(gsrc));
        }
    };

    float acc[2][8][4] = {};

    load_stage(0, 0);
    asm volatile("cp.async.commit_group;" ::: "memory");

    for (int kt = 0; kt < nkt; kt++) {
        const int st = kt & 1;
        if (kt + 1 < nkt) {
            load_stage(kt + 1, st ^ 1);
            asm volatile("cp.async.commit_group;" ::: "memory");
            asm volatile("cp.async.wait_group 1;" ::: "memory");
        } else {
            asm volatile("cp.async.wait_group 0;" ::: "memory");
        }
        __syncthreads();

        const uint32_t sAh_u = sbase + st * STAGE_B;
        const uint32_t sAl_u = sAh_u + TILE_B;
        const uint32_t sBh_u = sAh_u + 2 * TILE_B;
        const uint32_t sBl_u = sAh_u + 3 * TILE_B;

        #pragma unroll
        for (int ks = 0; ks < 2; ks++) {
            uint32_t ah[2][4], al[2][4];
            #pragma unroll
            for (int mb = 0; mb < 2; mb++) {
                const uint32_t off = (aoff + (uint32_t)(wm + mb * 16) * APAD + ks * 16) * 2;
                ldm_x4(ah[mb][0], ah[mb][1], ah[mb][2], ah[mb][3], sAh_u + off);
                ldm_x4(al[mb][0], al[mb][1], al[mb][2], al[mb][3], sAl_u + off);
            }
            #pragma unroll
            for (int nbp = 0; nbp < 4; nbp++) {
                const uint32_t off = (boff + (uint32_t)(wn + nbp * 16) * APAD + ks * 16) * 2;
                uint32_t bh[4], bl[4];
                ldm_x4(bh[0], bh[1], bh[2], bh[3], sBh_u + off);
                ldm_x4(bl[0], bl[1], bl[2], bl[3], sBl_u + off);
                #pragma unroll
                for (int h = 0; h < 2; h++) {
                    #pragma unroll
                    for (int mb = 0; mb < 2; mb++) {
                        float* d = acc[mb][nbp * 2 + h];
                        mma_bf16(d, ah[mb], bh + h * 2);
                        mma_bf16(d, ah[mb], bl + h * 2);
                        mma_bf16(d, al[mb], bh + h * 2);
                    }
                }
            }
        }
        __syncthreads();
    }

    const int mrow = lane >> 2, ncol = (lane & 3) * 2;
    #pragma unroll
    for (int mb = 0; mb < 2; mb++) {
        #pragma unroll
        for (int nb = 0; nb < 8; nb++) {
            const float* d = acc[mb][nb];
            const int m0 = bm + wm + mb * 16 + mrow;
            const int n = bn + wn + nb * 8 + ncol;
            if (m0 < M)
                *reinterpret_cast<float2*>(C + (size_t)m0 * N + n) = make_float2(d[0], d[1]);
            if (m0 + 8 < M)
                *reinterpret_cast<float2*>(C + (size_t)(m0 + 8) * N + n) = make_float2(d[2], d[3]);
        }
    }
}

// ================= prep kernels =================
// x -> Ah/Al with a*dinv_out[m], stride 320, zero-pad cols 300..319
__global__ void prep_x_kernel(const float* __restrict__ x, const float* __restrict__ dout,
                              __nv_bfloat16* __restrict__ Ah, __nv_bfloat16* __restrict__ Al) {
    int idx = blockIdx.x * blockDim.x + threadIdx.x;   // over M*160 pairs
    if (idx >= N_NODES * 160) return;
    int m = idx / 160, pk = idx - m * 160;
    int k = pk * 2;
    float a0 = 0.f, a1 = 0.f;
    if (k < 300) {
        float2 v = *reinterpret_cast<const float2*>(x + (size_t)m * 300 + k);
        float dv = dout[m];
        a0 = v.x * dv; a1 = v.y * dv;
    }
    uint32_t hi, lo; split2(a0, a1, hi, lo);
    ((uint32_t*)Ah)[(size_t)m * 160 + pk] = hi;
    ((uint32_t*)Al)[(size_t)m * 160 + pk] = lo;
}

// W[K,N] -> Wt hi/lo [N, K_pad] (k-major rows, zero pad)
__global__ void prep_w_kernel(const float* __restrict__ W,
                              __nv_bfloat16* __restrict__ Wh, __nv_bfloat16* __restrict__ Wl,
                              int K, int N, int Kpad) {
    int idx = blockIdx.x * blockDim.x + threadIdx.x;   // over N*Kpad/2 pairs
    int tot = N * (Kpad >> 1);
    if (idx >= tot) return;
    int pk = idx % (Kpad >> 1);
    int n = idx / (Kpad >> 1);
    int k = pk * 2;
    float w0 = 0.f, w1 = 0.f;
    if (k < K) { w0 = W[(size_t)k * N + n]; w1 = W[(size_t)(k + 1) * N + n]; }
    uint32_t hi, lo; split2(w0, w1, hi, lo);
    ((uint32_t*)Wh)[idx] = hi;
    ((uint32_t*)Wl)[idx] = lo;
}

// ================= CSC build =================
__global__ void zero_int_kernel(int4* __restrict__ p, int n4) {
    int i = blockIdx.x * blockDim.x + threadIdx.x;
    int stride = gridDim.x * blockDim.x;
    int4 z = make_int4(0, 0, 0, 0);
    for (; i < n4; i += stride) p[i] = z;
}

__global__ void hist_kernel(const int* __restrict__ src, const int* __restrict__ dst,
                            int* __restrict__ odeg, int* __restrict__ ideg, int nE) {
    int e = blockIdx.x * blockDim.x + threadIdx.x;
    if (e >= nE) return;
    int s = src[e], d = dst[e];
    if ((unsigned)s < N_NODES) atomicAdd(&odeg[s], 1);
    if ((unsigned)d < N_NODES) atomicAdd(&ideg[d], 1);
}

__global__ void dinv_kernel(const int* __restrict__ odeg, const int* __restrict__ ideg,
                            float* __restrict__ dout, float* __restrict__ din, int M) {
    int i = blockIdx.x * blockDim.x + threadIdx.x;
    if (i >= M) return;
    dout[i] = rsqrtf(fmaxf((float)odeg[i], 1.0f));
    din[i] = rsqrtf(fmaxf((float)ideg[i], 1.0f));
}

#define SCAN_BS 512
#define SCAN_NB ((N_NODES + SCAN_BS - 1) / SCAN_BS)  // 98

__global__ void blocksum_kernel(const int* __restrict__ deg, int* __restrict__ bsum) {
    __shared__ int sh[SCAN_BS];
    int i = blockIdx.x * SCAN_BS + threadIdx.x;
    sh[threadIdx.x] = (i < N_NODES) ? deg[i] : 0;
    __syncthreads();
    for (int s = SCAN_BS / 2; s > 0; s >>= 1) {
        if (threadIdx.x < s) sh[threadIdx.x] += sh[threadIdx.x + s];
        __syncthreads();
    }
    if (threadIdx.x == 0) bsum[blockIdx.x] = sh[0];
}

__global__ void scanpart_kernel(int* __restrict__ bsum, int nb) {
    __shared__ int sh[256];
    int t = threadIdx.x;
    int v = (t < nb) ? bsum[t] : 0;
    sh[t] = v;
    __syncthreads();
    for (int s = 1; s < 256; s <<= 1) {
        int add = (t >= s) ? sh[t - s] : 0;
        __syncthreads();
        sh[t] += add;
        __syncthreads();
    }
    if (t < nb) bsum[t] = sh[t] - v;  // exclusive
}

__global__ void offsets_kernel(const int* __restrict__ deg, const int* __restrict__ bsum,
                               int* __restrict__ off, int* __restrict__ cur) {
    __shared__ int sh[SCAN_BS];
    int t = threadIdx.x;
    int i = blockIdx.x * SCAN_BS + t;
    int v = (i < N_NODES) ? deg[i] : 0;
    sh[t] = v;
    __syncthreads();
    for (int s = 1; s < SCAN_BS; s <<= 1) {
        int add = (t >= s) ? sh[t - s] : 0;
        __syncthreads();
        sh[t] += add;
        __syncthreads();
    }
    if (i < N_NODES) {
        int excl = sh[t] - v + bsum[blockIdx.x];
        off[i] = excl;
        cur[i] = excl;
        if (i == N_NODES - 1) off[N_NODES] = excl + v;
    }
}

__global__ void fill_kernel(const int* __restrict__ src, const int* __restrict__ dst,
                            int* __restrict__ cur, int* __restrict__ csc, int nE) {
    int e = blockIdx.x * blockDim.x + threadIdx.x;
    if (e >= nE) return;
    int s = src[e], d = dst[e];
    if ((unsigned)s >= N_NODES || (unsigned)d >= N_NODES) return;
    int pos = atomicAdd(&cur[d], 1);
    csc[pos] = s;
}

// ================= pull aggregation (no atomics) =================
// warp per (node, chunk of 32 float4). acc = sum_{e:dst==node} h[src_e].
// layers 1-4: emit next-layer Ah/Al = split(leaky(acc*di + bias[n]) * dv)
// layer 5:    emit fp32 out = acc*di + bias[n]
__global__ __launch_bounds__(256)
void gather_kernel(const float* __restrict__ h, const int* __restrict__ off,
                   const int* __restrict__ csc, int N4, int cpn,
                   __nv_bfloat16* __restrict__ Ah, __nv_bfloat16* __restrict__ Al, int sNext,
                   const float* __restrict__ bias, const float* __restrict__ dinv_in,
                   const float* __restrict__ dinv_out, float* __restrict__ outF) {
    const int gw = blockIdx.x * 8 + (threadIdx.x >> 5);
    const int lane = threadIdx.x & 31;
    const int node = gw / cpn, chunk = gw - node * cpn;
    if (node >= N_NODES) return;
    const int c = chunk * 32 + lane;   // float4 column, < N4 by construction

    const float4* h4 = (const float4*)h;
    const int beg = off[node], end = off[node + 1];
    float4 acc = make_float4(0.f, 0.f, 0.f, 0.f);
    for (int j = beg; j < end; j++) {
        const int s = csc[j];          // warp-uniform broadcast
        float4 v = h4[(size_t)s * N4 + c];
        acc.x += v.x; acc.y += v.y; acc.z += v.z; acc.w += v.w;
    }
    const float di = dinv_in[node];
    const float4 b = ((const float4*)bias)[c];
    float v0 = fmaf(acc.x, di, b.x);
    float v1 = fmaf(acc.y, di, b.y);
    float v2 = fmaf(acc.z, di, b.z);
    float v3 = fmaf(acc.w, di, b.w);

    if (outF) {
        ((float4*)outF)[(size_t)node * N4 + c] = make_float4(v0, v1, v2, v3);
    } else {
        const float dv = dinv_out[node];
        v0 = ((v0 < 0.f) ? 0.01f * v0 : v0) * dv;
        v1 = ((v1 < 0.f) ? 0.01f * v1 : v1) * dv;
        v2 = ((v2 < 0.f) ? 0.01f * v2 : v2) * dv;
        v3 = ((v3 < 0.f) ? 0.01f * v3 : v3) * dv;
        uint32_t h0, l0, h1, l1;
        split2(v0, v1, h0, l0);
        split2(v2, v3, h1, l1);
        const size_t eo = (size_t)node * sNext + c * 4;
        *reinterpret_cast<uint2*>(Ah + eo) = make_uint2(h0, h1);
        *reinterpret_cast<uint2*>(Al + eo) = make_uint2(l0, l1);
    }
}

// ================= launch =================
extern "C" void kernel_launch(void* const* d_in, const int* in_sizes, int n_in,
                              void* d_out, int out_size) {
    const float* x = (const float*)d_in[0];
    const int* ei = (const int*)d_in[1];   // int32 (JAX x64 disabled)
    const float* W[5] = {(const float*)d_in[2], (const float*)d_in[4], (const float*)d_in[6],
                         (const float*)d_in[8], (const float*)d_in[10]};
    const float* B[5] = {(const float*)d_in[3], (const float*)d_in[5], (const float*)d_in[7],
                         (const float*)d_in[9], (const float*)d_in[11]};

    const int M = N_NODES;
    const int nE = N_EDGES;
    const int dims[6] = {300, 1024, 512, 256, 128, 2048};
    const int kpad[5] = {320, 1024, 512, 256, 128};   // A/W k-stride per layer
    const int* src = ei;
    const int* dstp = ei + nE;

    float *hP, *doutP, *dinP;
    __nv_bfloat16 *AhP, *AlP, *WhP, *WlP;
    int *idegP, *odegP, *offP, *curP, *cscP, *bsumP;
    cudaGetSymbolAddress((void**)&hP, g_h);
    cudaGetSymbolAddress((void**)&AhP, g_Ah);
    cudaGetSymbolAddress((void**)&AlP, g_Al);
    cudaGetSymbolAddress((void**)&WhP, g_Wh);
    cudaGetSymbolAddress((void**)&WlP, g_Wl);
    cudaGetSymbolAddress((void**)&doutP, g_dinv_out);
    cudaGetSymbolAddress((void**)&dinP, g_dinv_in);
    cudaGetSymbolAddress((void**)&idegP, g_ideg);
    cudaGetSymbolAddress((void**)&odegP, g_odeg);
    cudaGetSymbolAddress((void**)&offP, g_off);
    cudaGetSymbolAddress((void**)&curP, g_cur);
    cudaGetSymbolAddress((void**)&cscP, g_csc);
    cudaGetSymbolAddress((void**)&bsumP, g_bsum);

    cudaFuncSetAttribute(gemm_mma, cudaFuncAttributeMaxDynamicSharedMemorySize, SMEM_TOTAL_B);

    // ---- degrees + dinv + CSC build ----
    zero_int_kernel<<<32, 256>>>((int4*)idegP, N_NODES / 4);
    zero_int_kernel<<<32, 256>>>((int4*)odegP, N_NODES / 4);
    hist_kernel<<<(nE + 255) / 256, 256>>>(src, dstp, odegP, idegP, nE);
    dinv_kernel<<<(M + 255) / 256, 256>>>(odegP, idegP, doutP, dinP, M);
    blocksum_kernel<<<SCAN_NB, SCAN_BS>>>(idegP, bsumP);
    scanpart_kernel<<<1, 256>>>(bsumP, SCAN_NB);
    offsets_kernel<<<SCAN_NB, SCAN_BS>>>(idegP, bsumP, offP, curP);
    fill_kernel<<<(nE + 255) / 256, 256>>>(src, dstp, curP, cscP, nE);

    // ---- layer-1 A prep (x * dinv_out -> split bf16, stride 320) ----
    {
        int tot = M * 160;
        prep_x_kernel<<<(tot + 255) / 256, 256>>>(x, doutP, AhP, AlP);
    }

    // ---- 5 layers ----
    for (int l = 0; l < 5; l++) {
        const int K = dims[l], N = dims[l + 1], Kp = kpad[l];

        // weight transpose+split (tiny)
        int wtot = N * (Kp >> 1);
        prep_w_kernel<<<(wtot + 255) / 256, 256>>>(W[l], WhP, WlP, K, N, Kp);

        dim3 grid(N / 128, M_PAD / 128);
        gemm_mma<<<grid, 256, SMEM_TOTAL_B>>>(AhP, AlP, WhP, WlP, hP, M, N, Kp, Kp);

        // gather: emits next layer's split A (or final fp32 output)
        const int N4 = N / 4, cpn = N / 128;
        const int nwarp = M * cpn;
        if (l < 4) {
            gather_kernel<<<(nwarp + 7) / 8, 256>>>(hP, offP, cscP, N4, cpn,
                                                    AhP, AlP, kpad[l + 1], B[l], dinP, doutP, nullptr);
        } else {
            gather_kernel<<<(nwarp + 7) / 8, 256>>>(hP, offP, cscP, N4, cpn,
                                                    nullptr, nullptr, 0, B[4], dinP, doutP, (float*)d_out);
        }
    }
}

// round 8
// speedup vs baseline: 5.2464x; 1.3271x over previous
#include <cuda_runtime.h>
#include <cuda_bf16.h>
#include <cstdint>

// ---------------- problem constants ----------------
#define N_NODES 50000
#define N_EDGES 250000
#define M_PAD 50048           // 391 * 128
// dims: 300 -> 1024 -> 512 -> 256 -> 128 -> 2048

// ---------------- static device scratch ----------------
__device__ __align__(256) float g_t[(size_t)N_NODES * 512];             // GEMM fp32 out (layers 2-4)
__device__ __align__(256) float g_y[(size_t)N_NODES * 128];             // layer-4 activation fp32
__device__ __align__(256) __nv_bfloat16 g_Ah0[(size_t)M_PAD * 1024];    // split A ping
__device__ __align__(256) __nv_bfloat16 g_Al0[(size_t)M_PAD * 1024];
__device__ __align__(256) __nv_bfloat16 g_Ah1[(size_t)M_PAD * 1024];    // split A pong
__device__ __align__(256) __nv_bfloat16 g_Al1[(size_t)M_PAD * 1024];
__device__ __align__(256) __nv_bfloat16 g_Wh[600000];                   // transposed split W (hi)
__device__ __align__(256) __nv_bfloat16 g_Wl[600000];                   // transposed split W (lo)
__device__ __align__(256) float g_dinv_out[N_NODES];
__device__ __align__(256) float g_dinv_in[N_NODES];
// CSC structures
__device__ __align__(256) int g_ideg[N_NODES];
__device__ __align__(256) int g_odeg[N_NODES];
__device__ __align__(256) int g_off[N_NODES + 4];
__device__ __align__(256) int g_cur[N_NODES];
__device__ __align__(256) int g_csc[N_EDGES];
__device__ __align__(256) int g_bsum[128];

// ================= helpers =================
__device__ __forceinline__ uint32_t smem_u32(const void* p) {
    uint32_t a;
    asm("{ .reg .u64 t; cvta.to.shared.u64 t, %1; cvt.u32.u64 %0, t; }" : "=r"(a) : "l"(p));
    return a;
}

__device__ __forceinline__ void ldm_x4(uint32_t& r0, uint32_t& r1, uint32_t& r2, uint32_t& r3,
                                       uint32_t addr) {
    asm volatile("ldmatrix.sync.aligned.m8n8.x4.shared.b16 {%0,%1,%2,%3}, [%4];"
                 : "=r"(r0), "=r"(r1), "=r"(r2), "=r"(r3) : "r"(addr));
}

__device__ __forceinline__ void mma_bf16(float* d, const uint32_t* a, const uint32_t* b) {
    asm volatile("mma.sync.aligned.m16n8k16.row.col.f32.bf16.bf16.f32 "
                 "{%0,%1,%2,%3}, {%4,%5,%6,%7}, {%8,%9}, {%0,%1,%2,%3};"
                 : "+f"(d[0]), "+f"(d[1]), "+f"(d[2]), "+f"(d[3])
                 : "r"(a[0]), "r"(a[1]), "r"(a[2]), "r"(a[3]), "r"(b[0]), "r"(b[1]));
}

// fp32 -> bf16 hi/lo split, packed pair (low 16 bits = even-k element)
__device__ __forceinline__ void split2(float a, float b, uint32_t& hi, uint32_t& lo) {
    __nv_bfloat16 ah = __float2bfloat16(a);
    __nv_bfloat16 bh = __float2bfloat16(b);
    __nv_bfloat16 al = __float2bfloat16(a - __bfloat162float(ah));
    __nv_bfloat16 bl = __float2bfloat16(b - __bfloat162float(bh));
    hi = ((uint32_t)__bfloat16_as_ushort(bh) << 16) | (uint32_t)__bfloat16_as_ushort(ah);
    lo = ((uint32_t)__bfloat16_as_ushort(bl) << 16) | (uint32_t)__bfloat16_as_ushort(al);
}

// ================= pipelined bf16x3 mma.sync GEMM =================
// C = A @ Wt^T, A = Ah+Al [M_PAD, sA], Wt = Wh+Wl [N, sA] (k-major rows).
// Epilogue modes:
//  0: C[m][n] = d                         (fp32 t for gather_post)
//  1: A'(next) = split(leaky(d + bias[n]) * dout[m])   (stride sNext)
//  2: C[m][n] = d + bias[n]               (final output)
#define APAD 40                 // bf16 row stride in smem (80B)
#define TILE_B 10240            // 128*40*2 bytes per tile
#define STAGE_B 40960           // 4 tiles
#define SMEM_TOTAL_B 81920      // 2 stages

__global__ __launch_bounds__(256)
void gemm_mma(const __nv_bfloat16* __restrict__ Ah, const __nv_bfloat16* __restrict__ Al,
              const __nv_bfloat16* __restrict__ Wh, const __nv_bfloat16* __restrict__ Wl,
              float* __restrict__ C, int M, int N, int sA,
              int mode, const float* __restrict__ bias, const float* __restrict__ dout,
              __nv_bfloat16* __restrict__ oAh, __nv_bfloat16* __restrict__ oAl, int sNext) {
    extern __shared__ __nv_bfloat16 dsm[];
    const uint32_t sbase = smem_u32(dsm);

    const int tid = threadIdx.x, lane = tid & 31, wid = tid >> 5;
    const int bm = blockIdx.y * 128, bn = blockIdx.x * 128;
    const int wm = (wid >> 1) * 32, wn = (wid & 1) * 64;
    const int nkt = sA >> 5;

    const int g = lane >> 3, l8 = lane & 7;
    const uint32_t aoff = (uint32_t)(((g & 1) * 8 + l8) * APAD + (g >> 1) * 8);
    const uint32_t boff = (uint32_t)(((g >> 1) * 8 + l8) * APAD + (g & 1) * 8);

    auto load_stage = [&](int kt, int st) {
        const int k0 = kt << 5;
        #pragma unroll
        for (int it = 0; it < 8; it++) {
            const int idx = it * 256 + tid;
            const int t = idx >> 9, rc = idx & 511;
            const int r = rc >> 2, c = rc & 3;
            const __nv_bfloat16* gsrc;
            if (t == 0)      gsrc = Ah + (size_t)(bm + r) * sA + k0 + c * 8;
            else if (t == 1) gsrc = Al + (size_t)(bm + r) * sA + k0 + c * 8;
            else if (t == 2) gsrc = Wh + (size_t)(bn + r) * sA + k0 + c * 8;
            else             gsrc = Wl + (size_t)(bn + r) * sA + k0 + c * 8;
            const uint32_t d = sbase + st * STAGE_B + t * TILE_B + r * 80 + c * 16;
            asm volatile("cp.async.ca.shared.global [%0], [%1], 16;" :: "r"(d), "l"(gsrc));
        }
    };

    float acc[2][8][4] = {};

    load_stage(0, 0);
    asm volatile("cp.async.commit_group;" ::: "memory");

    for (int kt = 0; kt < nkt; kt++) {
        const int st = kt & 1;
        if (kt + 1 < nkt) {
            load_stage(kt + 1, st ^ 1);
            asm volatile("cp.async.commit_group;" ::: "memory");
            asm volatile("cp.async.wait_group 1;" ::: "memory");
        } else {
            asm volatile("cp.async.wait_group 0;" ::: "memory");
        }
        __syncthreads();

        const uint32_t sAh_u = sbase + st * STAGE_B;
        const uint32_t sAl_u = sAh_u + TILE_B;
        const uint32_t sBh_u = sAh_u + 2 * TILE_B;
        const uint32_t sBl_u = sAh_u + 3 * TILE_B;

        #pragma unroll
        for (int ks = 0; ks < 2; ks++) {
            uint32_t ah[2][4], al[2][4];
            #pragma unroll
            for (int mb = 0; mb < 2; mb++) {
                const uint32_t off = (aoff + (uint32_t)(wm + mb * 16) * APAD + ks * 16) * 2;
                ldm_x4(ah[mb][0], ah[mb][1], ah[mb][2], ah[mb][3], sAh_u + off);
                ldm_x4(al[mb][0], al[mb][1], al[mb][2], al[mb][3], sAl_u + off);
            }
            #pragma unroll
            for (int nbp = 0; nbp < 4; nbp++) {
                const uint32_t off = (boff + (uint32_t)(wn + nbp * 16) * APAD + ks * 16) * 2;
                uint32_t bh[4], bl[4];
                ldm_x4(bh[0], bh[1], bh[2], bh[3], sBh_u + off);
                ldm_x4(bl[0], bl[1], bl[2], bl[3], sBl_u + off);
                #pragma unroll
                for (int h = 0; h < 2; h++) {
                    #pragma unroll
                    for (int mb = 0; mb < 2; mb++) {
                        float* d = acc[mb][nbp * 2 + h];
                        mma_bf16(d, ah[mb], bh + h * 2);
                        mma_bf16(d, ah[mb], bl + h * 2);
                        mma_bf16(d, al[mb], bh + h * 2);
                    }
                }
            }
        }
        __syncthreads();
    }

    const int mrow = lane >> 2, ncol = (lane & 3) * 2;
    #pragma unroll
    for (int mb = 0; mb < 2; mb++) {
        const int m0 = bm + wm + mb * 16 + mrow;
        float dv0 = 0.f, dv1 = 0.f;
        if (mode == 1) {
            if (m0 < M) dv0 = dout[m0];
            if (m0 + 8 < M) dv1 = dout[m0 + 8];
        }
        #pragma unroll
        for (int nb = 0; nb < 8; nb++) {
            const float* d = acc[mb][nb];
            const int n = bn + wn + nb * 8 + ncol;
            if (mode == 0) {
                if (m0 < M)
                    *reinterpret_cast<float2*>(C + (size_t)m0 * N + n) = make_float2(d[0], d[1]);
                if (m0 + 8 < M)
                    *reinterpret_cast<float2*>(C + (size_t)(m0 + 8) * N + n) = make_float2(d[2], d[3]);
            } else if (mode == 2) {
                const float b0 = bias[n], b1 = bias[n + 1];
                if (m0 < M)
                    *reinterpret_cast<float2*>(C + (size_t)m0 * N + n) = make_float2(d[0] + b0, d[1] + b1);
                if (m0 + 8 < M)
                    *reinterpret_cast<float2*>(C + (size_t)(m0 + 8) * N + n) = make_float2(d[2] + b0, d[3] + b1);
            } else {
                const float b0 = bias[n], b1 = bias[n + 1];
                if (m0 < M) {
                    float v0 = d[0] + b0, v1 = d[1] + b1;
                    v0 = ((v0 < 0.f) ? 0.01f * v0 : v0) * dv0;
                    v1 = ((v1 < 0.f) ? 0.01f * v1 : v1) * dv0;
                    uint32_t hi, lo; split2(v0, v1, hi, lo);
                    *reinterpret_cast<uint32_t*>(oAh + (size_t)m0 * sNext + n) = hi;
                    *reinterpret_cast<uint32_t*>(oAl + (size_t)m0 * sNext + n) = lo;
                }
                if (m0 + 8 < M) {
                    float v0 = d[2] + b0, v1 = d[3] + b1;
                    v0 = ((v0 < 0.f) ? 0.01f * v0 : v0) * dv1;
                    v1 = ((v1 < 0.f) ? 0.01f * v1 : v1) * dv1;
                    uint32_t hi, lo; split2(v0, v1, hi, lo);
                    *reinterpret_cast<uint32_t*>(oAh + (size_t)(m0 + 8) * sNext + n) = hi;
                    *reinterpret_cast<uint32_t*>(oAl + (size_t)(m0 + 8) * sNext + n) = lo;
                }
            }
        }
    }
}

// ================= W prep: W[K,N] -> Wt hi/lo [N, Kpad] =================
__global__ void prep_w_kernel(const float* __restrict__ W,
                              __nv_bfloat16* __restrict__ Wh, __nv_bfloat16* __restrict__ Wl,
                              int K, int N, int Kpad) {
    int idx = blockIdx.x * blockDim.x + threadIdx.x;
    int tot = N * (Kpad >> 1);
    if (idx >= tot) return;
    int pk = idx % (Kpad >> 1);
    int n = idx / (Kpad >> 1);
    int k = pk * 2;
    float w0 = 0.f, w1 = 0.f;
    if (k < K) { w0 = W[(size_t)k * N + n]; w1 = W[(size_t)(k + 1) * N + n]; }
    uint32_t hi, lo; split2(w0, w1, hi, lo);
    ((uint32_t*)Wh)[idx] = hi;
    ((uint32_t*)Wl)[idx] = lo;
}

// ================= CSC build =================
__global__ void zero_int_kernel(int4* __restrict__ p, int n4) {
    int i = blockIdx.x * blockDim.x + threadIdx.x;
    int stride = gridDim.x * blockDim.x;
    int4 z = make_int4(0, 0, 0, 0);
    for (; i < n4; i += stride) p[i] = z;
}

__global__ void hist_kernel(const int* __restrict__ src, const int* __restrict__ dst,
                            int* __restrict__ odeg, int* __restrict__ ideg, int nE) {
    int e = blockIdx.x * blockDim.x + threadIdx.x;
    if (e >= nE) return;
    int s = src[e], d = dst[e];
    if ((unsigned)s < N_NODES) atomicAdd(&odeg[s], 1);
    if ((unsigned)d < N_NODES) atomicAdd(&ideg[d], 1);
}

__global__ void dinv_kernel(const int* __restrict__ odeg, const int* __restrict__ ideg,
                            float* __restrict__ dout, float* __restrict__ din, int M) {
    int i = blockIdx.x * blockDim.x + threadIdx.x;
    if (i >= M) return;
    dout[i] = rsqrtf(fmaxf((float)odeg[i], 1.0f));
    din[i] = rsqrtf(fmaxf((float)ideg[i], 1.0f));
}

#define SCAN_BS 512
#define SCAN_NB ((N_NODES + SCAN_BS - 1) / SCAN_BS)  // 98

__global__ void blocksum_kernel(const int* __restrict__ deg, int* __restrict__ bsum) {
    __shared__ int sh[SCAN_BS];
    int i = blockIdx.x * SCAN_BS + threadIdx.x;
    sh[threadIdx.x] = (i < N_NODES) ? deg[i] : 0;
    __syncthreads();
    for (int s = SCAN_BS / 2; s > 0; s >>= 1) {
        if (threadIdx.x < s) sh[threadIdx.x] += sh[threadIdx.x + s];
        __syncthreads();
    }
    if (threadIdx.x == 0) bsum[blockIdx.x] = sh[0];
}

__global__ void scanpart_kernel(int* __restrict__ bsum, int nb) {
    __shared__ int sh[256];
    int t = threadIdx.x;
    int v = (t < nb) ? bsum[t] : 0;
    sh[t] = v;
    __syncthreads();
    for (int s = 1; s < 256; s <<= 1) {
        int add = (t >= s) ? sh[t - s] : 0;
        __syncthreads();
        sh[t] += add;
        __syncthreads();
    }
    if (t < nb) bsum[t] = sh[t] - v;  // exclusive
}

__global__ void offsets_kernel(const int* __restrict__ deg, const int* __restrict__ bsum,
                               int* __restrict__ off, int* __restrict__ cur) {
    __shared__ int sh[SCAN_BS];
    int t = threadIdx.x;
    int i = blockIdx.x * SCAN_BS + t;
    int v = (i < N_NODES) ? deg[i] : 0;
    sh[t] = v;
    __syncthreads();
    for (int s = 1; s < SCAN_BS; s <<= 1) {
        int add = (t >= s) ? sh[t - s] : 0;
        __syncthreads();
        sh[t] += add;
        __syncthreads();
    }
    if (i < N_NODES) {
        int excl = sh[t] - v + bsum[blockIdx.x];
        off[i] = excl;
        cur[i] = excl;
        if (i == N_NODES - 1) off[N_NODES] = excl + v;
    }
}

__global__ void fill_kernel(const int* __restrict__ src, const int* __restrict__ dst,
                            int* __restrict__ cur, int* __restrict__ csc, int nE) {
    int e = blockIdx.x * blockDim.x + threadIdx.x;
    if (e >= nE) return;
    int s = src[e], d = dst[e];
    if ((unsigned)s >= N_NODES || (unsigned)d >= N_NODES) return;
    int pos = atomicAdd(&cur[d], 1);
    csc[pos] = s;
}

// ================= gather_pre: u = dinv_in ⊙ S (opt dout ⊙) y  -> split bf16 =================
// warp per node; K4 = fp32 float4 row width; Kpad4 >= K4 zero-padded.
__global__ __launch_bounds__(256)
void gather_pre(const float* __restrict__ y, const float* __restrict__ dout,
                const int* __restrict__ off, const int* __restrict__ csc,
                int K4, int Kpad4,
                __nv_bfloat16* __restrict__ Ah, __nv_bfloat16* __restrict__ Al, int sNext,
                const float* __restrict__ dinv_in) {
    const int node = blockIdx.x * 8 + (threadIdx.x >> 5);
    if (node >= N_NODES) return;
    const int lane = threadIdx.x & 31;
    const int beg = off[node], end = off[node + 1];
    const float di = dinv_in[node];
    const float4* y4 = (const float4*)y;

    for (int c = lane; c < Kpad4; c += 32) {
        float4 acc = make_float4(0.f, 0.f, 0.f, 0.f);
        if (c < K4) {
            for (int j = beg; j < end; j++) {
                const int s = csc[j];
                float4 v = y4[(size_t)s * K4 + c];
                const float sc = dout ? dout[s] : 1.0f;
                acc.x += v.x * sc; acc.y += v.y * sc; acc.z += v.z * sc; acc.w += v.w * sc;
            }
        }
        uint32_t h0, l0, h1, l1;
        split2(acc.x * di, acc.y * di, h0, l0);
        split2(acc.z * di, acc.w * di, h1, l1);
        const size_t eo = (size_t)node * sNext + c * 4;
        *reinterpret_cast<uint2*>(Ah + eo) = make_uint2(h0, h1);
        *reinterpret_cast<uint2*>(Al + eo) = make_uint2(l0, l1);
    }
}

// ================= gather_post: agg = S t; act = leaky(dinv_in⊙agg + b) ⊙ dinv_out =================
// mode 0: emit split bf16 A(next) (stride sNext); mode 1: emit fp32 act (width N4*4)
__global__ __launch_bounds__(256)
void gather_post(const float* __restrict__ t, const int* __restrict__ off,
                 const int* __restrict__ csc, int N4, int cpn,
                 __nv_bfloat16* __restrict__ Ah, __nv_bfloat16* __restrict__ Al, int sNext,
                 const float* __restrict__ bias, const float* __restrict__ dinv_in,
                 const float* __restrict__ dinv_out, float* __restrict__ outF) {
    const int gw = blockIdx.x * 8 + (threadIdx.x >> 5);
    const int lane = threadIdx.x & 31;
    const int node = gw / cpn, chunk = gw - node * cpn;
    if (node >= N_NODES) return;
    const int c = chunk * 32 + lane;

    const float4* t4 = (const float4*)t;
    const int beg = off[node], end = off[node + 1];
    float4 acc = make_float4(0.f, 0.f, 0.f, 0.f);
    for (int j = beg; j < end; j++) {
        const int s = csc[j];
        float4 v = t4[(size_t)s * N4 + c];
        acc.x += v.x; acc.y += v.y; acc.z += v.z; acc.w += v.w;
    }
    const float di = dinv_in[node];
    const float dv = dinv_out[node];
    const float4 b = ((const float4*)bias)[c];
    float v0 = fmaf(acc.x, di, b.x);
    float v1 = fmaf(acc.y, di, b.y);
    float v2 = fmaf(acc.z, di, b.z);
    float v3 = fmaf(acc.w, di, b.w);
    v0 = ((v0 < 0.f) ? 0.01f * v0 : v0) * dv;
    v1 = ((v1 < 0.f) ? 0.01f * v1 : v1) * dv;
    v2 = ((v2 < 0.f) ? 0.01f * v2 : v2) * dv;
    v3 = ((v3 < 0.f) ? 0.01f * v3 : v3) * dv;

    if (outF) {
        ((float4*)outF)[(size_t)node * N4 + c] = make_float4(v0, v1, v2, v3);
    } else {
        uint32_t h0, l0, h1, l1;
        split2(v0, v1, h0, l0);
        split2(v2, v3, h1, l1);
        const size_t eo = (size_t)node * sNext + c * 4;
        *reinterpret_cast<uint2*>(Ah + eo) = make_uint2(h0, h1);
        *reinterpret_cast<uint2*>(Al + eo) = make_uint2(l0, l1);
    }
}

// ================= launch =================
extern "C" void kernel_launch(void* const* d_in, const int* in_sizes, int n_in,
                              void* d_out, int out_size) {
    const float* x = (const float*)d_in[0];
    const int* ei = (const int*)d_in[1];   // int32 (JAX x64 disabled)
    const float* W[5] = {(const float*)d_in[2], (const float*)d_in[4], (const float*)d_in[6],
                         (const float*)d_in[8], (const float*)d_in[10]};
    const float* B[5] = {(const float*)d_in[3], (const float*)d_in[5], (const float*)d_in[7],
                         (const float*)d_in[9], (const float*)d_in[11]};

    const int M = N_NODES;
    const int nE = N_EDGES;
    const int* src = ei;
    const int* dstp = ei + nE;

    float *tP, *yP, *doutP, *dinP;
    __nv_bfloat16 *Ah0, *Al0, *Ah1, *Al1, *WhP, *WlP;
    int *idegP, *odegP, *offP, *curP, *cscP, *bsumP;
    cudaGetSymbolAddress((void**)&tP, g_t);
    cudaGetSymbolAddress((void**)&yP, g_y);
    cudaGetSymbolAddress((void**)&Ah0, g_Ah0);
    cudaGetSymbolAddress((void**)&Al0, g_Al0);
    cudaGetSymbolAddress((void**)&Ah1, g_Ah1);
    cudaGetSymbolAddress((void**)&Al1, g_Al1);
    cudaGetSymbolAddress((void**)&WhP, g_Wh);
    cudaGetSymbolAddress((void**)&WlP, g_Wl);
    cudaGetSymbolAddress((void**)&doutP, g_dinv_out);
    cudaGetSymbolAddress((void**)&dinP, g_dinv_in);
    cudaGetSymbolAddress((void**)&idegP, g_ideg);
    cudaGetSymbolAddress((void**)&odegP, g_odeg);
    cudaGetSymbolAddress((void**)&offP, g_off);
    cudaGetSymbolAddress((void**)&curP, g_cur);
    cudaGetSymbolAddress((void**)&cscP, g_csc);
    cudaGetSymbolAddress((void**)&bsumP, g_bsum);

    cudaFuncSetAttribute(gemm_mma, cudaFuncAttributeMaxDynamicSharedMemorySize, SMEM_TOTAL_B);

    // ---- degrees + dinv + CSC build ----
    zero_int_kernel<<<32, 256>>>((int4*)idegP, N_NODES / 4);
    zero_int_kernel<<<32, 256>>>((int4*)odegP, N_NODES / 4);
    hist_kernel<<<(nE + 255) / 256, 256>>>(src, dstp, odegP, idegP, nE);
    dinv_kernel<<<(M + 255) / 256, 256>>>(odegP, idegP, doutP, dinP, M);
    blocksum_kernel<<<SCAN_NB, SCAN_BS>>>(idegP, bsumP);
    scanpart_kernel<<<1, 256>>>(bsumP, SCAN_NB);
    offsets_kernel<<<SCAN_NB, SCAN_BS>>>(idegP, bsumP, offP, curP);
    fill_kernel<<<(nE + 255) / 256, 256>>>(src, dstp, curP, cscP, nE);

    const int nwB = (M * 8 + 2047) / 2048;   // helper for warp-per-node grids (8 warps/CTA)

    // ---- Layer 1 (aggregate-first, K=300->320, N=1024) ----
    gather_pre<<<(M + 7) / 8, 256>>>(x, doutP, offP, cscP, 75, 80, Ah0, Al0, 320, dinP);
    prep_w_kernel<<<(1024 * 160 + 255) / 256, 256>>>(W[0], WhP, WlP, 300, 1024, 320);
    {   // epilogue: +b1, leaky, *dout -> split A1 (stride 1024)
        dim3 grid(1024 / 128, M_PAD / 128);
        gemm_mma<<<grid, 256, SMEM_TOTAL_B>>>(Ah0, Al0, WhP, WlP, nullptr, M, 1024, 320,
                                              1, B[0], doutP, Ah1, Al1, 1024);
    }

    // ---- Layer 2 (aggregate-after, K=1024, N=512) ----
    prep_w_kernel<<<(512 * 512 + 255) / 256, 256>>>(W[1], WhP, WlP, 1024, 512, 1024);
    {
        dim3 grid(512 / 128, M_PAD / 128);
        gemm_mma<<<grid, 256, SMEM_TOTAL_B>>>(Ah1, Al1, WhP, WlP, tP, M, 512, 1024,
                                              0, nullptr, nullptr, nullptr, nullptr, 0);
    }
    gather_post<<<(M * 4 + 7) / 8, 256>>>(tP, offP, cscP, 128, 4, Ah0, Al0, 512,
                                          B[1], dinP, doutP, nullptr);

    // ---- Layer 3 (aggregate-after, K=512, N=256) ----
    prep_w_kernel<<<(256 * 256 + 255) / 256, 256>>>(W[2], WhP, WlP, 512, 256, 512);
    {
        dim3 grid(256 / 128, M_PAD / 128);
        gemm_mma<<<grid, 256, SMEM_TOTAL_B>>>(Ah0, Al0, WhP, WlP, tP, M, 256, 512,
                                              0, nullptr, nullptr, nullptr, nullptr, 0);
    }
    gather_post<<<(M * 2 + 7) / 8, 256>>>(tP, offP, cscP, 64, 2, Ah1, Al1, 256,
                                          B[2], dinP, doutP, nullptr);

    // ---- Layer 4 (aggregate-after, K=256, N=128) -> fp32 y (act4 * dinv_out) ----
    prep_w_kernel<<<(128 * 128 + 255) / 256, 256>>>(W[3], WhP, WlP, 256, 128, 256);
    {
        dim3 grid(128 / 128, M_PAD / 128);
        gemm_mma<<<grid, 256, SMEM_TOTAL_B>>>(Ah1, Al1, WhP, WlP, tP, M, 128, 256,
                                              0, nullptr, nullptr, nullptr, nullptr, 0);
    }
    gather_post<<<(M + 7) / 8, 256>>>(tP, offP, cscP, 32, 1, nullptr, nullptr, 0,
                                      B[3], dinP, doutP, yP);

    // ---- Layer 5 (aggregate-first, K=128, N=2048) ----
    gather_pre<<<(M + 7) / 8, 256>>>(yP, nullptr, offP, cscP, 32, 32, Ah0, Al0, 128, dinP);
    prep_w_kernel<<<(2048 * 64 + 255) / 256, 256>>>(W[4], WhP, WlP, 128, 2048, 128);
    {   // epilogue: +b5 -> d_out fp32
        dim3 grid(2048 / 128, M_PAD / 128);
        gemm_mma<<<grid, 256, SMEM_TOTAL_B>>>(Ah0, Al0, WhP, WlP, (float*)d_out, M, 2048, 128,
                                              2, B[4], nullptr, nullptr, nullptr, 0);
    }
    (void)nwB;
}